// round 6
// baseline (speedup 1.0000x reference)
#include <cuda_runtime.h>
#include <cuda_bf16.h>

#define NN 50000
#define EE 600000
#define DD 128

// ---- scratch (device globals; referenced directly from device code only) ----
__device__ float g_dinv[NN];          // degree accum, then rsqrt(deg+1)
__device__ float g_norm[EE];          // per-edge norm
__device__ float g_h[NN * DD];        // x@W1, then relu_out@W2
__device__ float g_agg[NN * DD];      // layer-1 aggregate / relu output

// ---------------- init ----------------
__global__ void init_kernel(float* __restrict__ out) {
    int i = blockIdx.x * blockDim.x + threadIdx.x;
    int stride = gridDim.x * blockDim.x;
    for (int idx = i; idx < NN * DD; idx += stride) {
        g_agg[idx] = 0.0f;
        out[idx] = 0.0f;
    }
    for (int idx = i; idx < NN; idx += stride) g_dinv[idx] = 0.0f;
}

// deg[dst] += ew[e]   (edge_index is INT32: jax x64-disabled demotes int64)
__global__ void deg_kernel(const int* __restrict__ ei,
                           const float* __restrict__ ew) {
    int e = blockIdx.x * blockDim.x + threadIdx.x;
    if (e < EE) {
        int dst = ei[EE + e];
        atomicAdd(&g_dinv[dst], ew[e]);
    }
}

// dinv = rsqrt(deg + 1)  (always > 0, matches reference's where(deg>0))
__global__ void dinv_kernel() {
    int i = blockIdx.x * blockDim.x + threadIdx.x;
    if (i < NN) g_dinv[i] = rsqrtf(g_dinv[i] + 1.0f);
}

// norm[e] = dinv[src] * ew[e] * dinv[dst]
__global__ void norm_kernel(const int* __restrict__ ei,
                            const float* __restrict__ ew) {
    int e = blockIdx.x * blockDim.x + threadIdx.x;
    if (e < EE) {
        int src = ei[e];
        int dst = ei[EE + e];
        g_norm[e] = g_dinv[src] * ew[e] * g_dinv[dst];
    }
}

// ---------------- GEMM: C[nrows x 128] = A[nrows x 128] @ W[128 x 128] ----------------
// 256 threads -> 64 rows/block. Thread (r = tid/4, cg = tid%4) computes
// cols {cg, cg+4, ..., cg+124} of row r (32 accumulators).
#define GR 64        // rows per block
#define KT 32        // k tile

// GEMM layer 1: A = x (harness input), C = g_h
__global__ __launch_bounds__(256, 4)
void gemm1_kernel(const float* __restrict__ A, const float* __restrict__ W) {
    __shared__ float xs[GR][KT + 1];
    __shared__ float ws[KT][DD];
    int tid = threadIdx.x;
    int r = tid >> 2, cg = tid & 3;
    int row0 = blockIdx.x * GR;
    float acc[32];
#pragma unroll
    for (int j = 0; j < 32; j++) acc[j] = 0.0f;
    for (int k0 = 0; k0 < DD; k0 += KT) {
#pragma unroll
        for (int t = 0; t < 8; t++) {
            int idx = tid + t * 256;
            int ir = idx >> 5, ik = idx & 31;
            int grow = row0 + ir;
            xs[ir][ik] = (grow < NN) ? A[grow * DD + k0 + ik] : 0.0f;
        }
#pragma unroll
        for (int t = 0; t < 16; t++) {
            int idx = tid + t * 256;
            int ik = idx >> 7, ic = idx & 127;
            ws[ik][ic] = W[(k0 + ik) * DD + ic];
        }
        __syncthreads();
#pragma unroll
        for (int kk = 0; kk < KT; kk++) {
            float xv = xs[r][kk];
#pragma unroll
            for (int j = 0; j < 32; j++) acc[j] += xv * ws[kk][cg + 4 * j];
        }
        __syncthreads();
    }
    int grow = row0 + r;
    if (grow < NN) {
#pragma unroll
        for (int j = 0; j < 32; j++) g_h[grow * DD + cg + 4 * j] = acc[j];
    }
}

// GEMM layer 2: A = g_agg, C = g_h
__global__ __launch_bounds__(256, 4)
void gemm2_kernel(const float* __restrict__ W) {
    __shared__ float xs[GR][KT + 1];
    __shared__ float ws[KT][DD];
    int tid = threadIdx.x;
    int r = tid >> 2, cg = tid & 3;
    int row0 = blockIdx.x * GR;
    float acc[32];
#pragma unroll
    for (int j = 0; j < 32; j++) acc[j] = 0.0f;
    for (int k0 = 0; k0 < DD; k0 += KT) {
#pragma unroll
        for (int t = 0; t < 8; t++) {
            int idx = tid + t * 256;
            int ir = idx >> 5, ik = idx & 31;
            int grow = row0 + ir;
            xs[ir][ik] = (grow < NN) ? g_agg[grow * DD + k0 + ik] : 0.0f;
        }
#pragma unroll
        for (int t = 0; t < 16; t++) {
            int idx = tid + t * 256;
            int ik = idx >> 7, ic = idx & 127;
            ws[ik][ic] = W[(k0 + ik) * DD + ic];
        }
        __syncthreads();
#pragma unroll
        for (int kk = 0; kk < KT; kk++) {
            float xv = xs[r][kk];
#pragma unroll
            for (int j = 0; j < 32; j++) acc[j] += xv * ws[kk][cg + 4 * j];
        }
        __syncthreads();
    }
    int grow = row0 + r;
    if (grow < NN) {
#pragma unroll
        for (int j = 0; j < 32; j++) g_h[grow * DD + cg + 4 * j] = acc[j];
    }
}

// ---------------- edge scatter: agg[dst] += norm[e] * h[src] ----------------
// one warp per edge; each lane: float4 gather + 4 atomics

// layer 1: g_h -> g_agg
__global__ __launch_bounds__(256)
void scatter1_kernel(const int* __restrict__ ei) {
    int gtid = blockIdx.x * blockDim.x + threadIdx.x;
    int e = gtid >> 5;
    int lane = gtid & 31;
    if (e >= EE) return;
    int src = ei[e];
    int dst = ei[EE + e];
    float nrm = g_norm[e];
    const float4 v = *reinterpret_cast<const float4*>(&g_h[src * DD + lane * 4]);
    float* a = &g_agg[dst * DD + lane * 4];
    atomicAdd(a + 0, nrm * v.x);
    atomicAdd(a + 1, nrm * v.y);
    atomicAdd(a + 2, nrm * v.z);
    atomicAdd(a + 3, nrm * v.w);
}

// layer 2: g_h -> out (harness buffer)
__global__ __launch_bounds__(256)
void scatter2_kernel(const int* __restrict__ ei, float* __restrict__ out) {
    int gtid = blockIdx.x * blockDim.x + threadIdx.x;
    int e = gtid >> 5;
    int lane = gtid & 31;
    if (e >= EE) return;
    int src = ei[e];
    int dst = ei[EE + e];
    float nrm = g_norm[e];
    const float4 v = *reinterpret_cast<const float4*>(&g_h[src * DD + lane * 4]);
    float* a = &out[dst * DD + lane * 4];
    atomicAdd(a + 0, nrm * v.x);
    atomicAdd(a + 1, nrm * v.y);
    atomicAdd(a + 2, nrm * v.z);
    atomicAdd(a + 3, nrm * v.w);
}

// ---------------- epilogues ----------------
// layer 1: g_agg = relu(g_agg + g_h*dinv^2 + b1)
__global__ __launch_bounds__(256)
void post1_kernel(const float* __restrict__ b) {
    int idx = blockIdx.x * blockDim.x + threadIdx.x;
    if (idx >= NN * DD) return;
    int i = idx >> 7;
    int c = idx & 127;
    float di = g_dinv[i];
    float val = g_agg[idx] + g_h[idx] * di * di + b[c];
    g_agg[idx] = fmaxf(val, 0.0f);
}

// layer 2: out = out + g_h*dinv^2 + b2
__global__ __launch_bounds__(256)
void post2_kernel(const float* __restrict__ b, float* __restrict__ out) {
    int idx = blockIdx.x * blockDim.x + threadIdx.x;
    if (idx >= NN * DD) return;
    int i = idx >> 7;
    int c = idx & 127;
    float di = g_dinv[i];
    out[idx] = out[idx] + g_h[idx] * di * di + b[c];
}

// ---------------- launch: kernel launches ONLY ----------------
extern "C" void kernel_launch(void* const* d_in, const int* in_sizes, int n_in,
                              void* d_out, int out_size) {
    const float* x  = (const float*)d_in[0];
    const int*   ei = (const int*)d_in[1];     // int32! (jax x64 disabled)
    const float* ew = (const float*)d_in[2];
    const float* W1 = (const float*)d_in[3];
    const float* b1 = (const float*)d_in[4];
    const float* W2 = (const float*)d_in[5];
    const float* b2 = (const float*)d_in[6];
    float* out = (float*)d_out;

    const int NB_N  = (NN + 255) / 256;
    const int NB_E  = (EE + 255) / 256;
    const int NB_ND = (NN * DD + 255) / 256;
    const int NB_SC = (int)(((long long)EE * 32 + 255) / 256);
    const int NB_GM = (NN + GR - 1) / GR;

    init_kernel<<<2048, 256>>>(out);

    deg_kernel<<<NB_E, 256>>>(ei, ew);
    dinv_kernel<<<NB_N, 256>>>();
    norm_kernel<<<NB_E, 256>>>(ei, ew);

    // ---- layer 1 ----
    gemm1_kernel<<<NB_GM, 256>>>(x, W1);
    scatter1_kernel<<<NB_SC, 256>>>(ei);
    post1_kernel<<<NB_ND, 256>>>(b1);

    // ---- layer 2 ----
    gemm2_kernel<<<NB_GM, 256>>>(W2);
    scatter2_kernel<<<NB_SC, 256>>>(ei, out);
    post2_kernel<<<NB_ND, 256>>>(b2, out);
}

// round 7
// speedup vs baseline: 2.2588x; 2.2588x over previous
#include <cuda_runtime.h>
#include <cuda_bf16.h>

#define NN 50000
#define EE 600000
#define DD 128

// ---- scratch (device globals; referenced directly from device code only) ----
__device__ float g_dinv[NN];
__device__ float g_norm[EE];
__device__ float g_h[NN * DD];        // GEMM output (both layers)
__device__ float g_agg[NN * DD];      // layer-1 aggregate / relu output

// ---------------- init ----------------
__global__ void init_kernel(float* __restrict__ out) {
    int i = blockIdx.x * blockDim.x + threadIdx.x;
    int stride = gridDim.x * blockDim.x;
    float4 z = make_float4(0.f, 0.f, 0.f, 0.f);
    float4* agg4 = reinterpret_cast<float4*>(g_agg);
    float4* out4 = reinterpret_cast<float4*>(out);
    for (int idx = i; idx < NN * DD / 4; idx += stride) {
        agg4[idx] = z;
        out4[idx] = z;
    }
    for (int idx = i; idx < NN; idx += stride) g_dinv[idx] = 0.0f;
}

// deg[dst] += ew[e]   (edge_index is int32)
__global__ void deg_kernel(const int* __restrict__ ei,
                           const float* __restrict__ ew) {
    int e = blockIdx.x * blockDim.x + threadIdx.x;
    if (e < EE) atomicAdd(&g_dinv[ei[EE + e]], ew[e]);
}

// dinv = rsqrt(deg + 1)
__global__ void dinv_kernel() {
    int i = blockIdx.x * blockDim.x + threadIdx.x;
    if (i < NN) g_dinv[i] = rsqrtf(g_dinv[i] + 1.0f);
}

// norm[e] = dinv[src] * ew[e] * dinv[dst]
__global__ void norm_kernel(const int* __restrict__ ei,
                            const float* __restrict__ ew) {
    int e = blockIdx.x * blockDim.x + threadIdx.x;
    if (e < EE) g_norm[e] = g_dinv[ei[e]] * ew[e] * g_dinv[ei[EE + e]];
}

// ---------------- GEMM: C[NN x 128] = A[NN x 128] @ W[128 x 128] ----------------
// 128x128 block tile, BK=8, 256 threads, 8x8 micro-tile per thread.
// src_sel: 0 -> A = x (param), 1 -> A = g_agg. C = g_h always.
#define BM 128
#define BK 8

__global__ __launch_bounds__(256, 2)
void gemm_kernel(const float* __restrict__ x, const float* __restrict__ W,
                 int src_sel) {
    __shared__ float As[BK][BM];       // transposed A tile
    __shared__ float Bs[BK][DD];

    const float* __restrict__ A = src_sel ? g_agg : x;

    int tid = threadIdx.x;
    int row0 = blockIdx.x * BM;
    int tm = tid >> 4;                 // 0..15
    int tn = tid & 15;                 // 0..15

    float acc[8][8];
#pragma unroll
    for (int i = 0; i < 8; i++)
#pragma unroll
        for (int j = 0; j < 8; j++) acc[i][j] = 0.0f;

    // A-load mapping: thread loads one float4 of A per k-tile
    int a_row = tid >> 1;              // 0..127
    int a_k4  = (tid & 1) * 4;         // 0 or 4
    // B-load mapping
    int b_row = tid >> 5;              // 0..7
    int b_col = (tid & 31) * 4;        // 0..124

    for (int k0 = 0; k0 < DD; k0 += BK) {
        int grow = row0 + a_row;
        float4 av = make_float4(0.f, 0.f, 0.f, 0.f);
        if (grow < NN)
            av = *reinterpret_cast<const float4*>(&A[grow * DD + k0 + a_k4]);
        As[a_k4 + 0][a_row] = av.x;
        As[a_k4 + 1][a_row] = av.y;
        As[a_k4 + 2][a_row] = av.z;
        As[a_k4 + 3][a_row] = av.w;

        *reinterpret_cast<float4*>(&Bs[b_row][b_col]) =
            *reinterpret_cast<const float4*>(&W[(k0 + b_row) * DD + b_col]);
        __syncthreads();

#pragma unroll
        for (int kk = 0; kk < BK; kk++) {
            float a[8], b[8];
            *reinterpret_cast<float4*>(a)     = *reinterpret_cast<float4*>(&As[kk][tm * 8]);
            *reinterpret_cast<float4*>(a + 4) = *reinterpret_cast<float4*>(&As[kk][tm * 8 + 4]);
            *reinterpret_cast<float4*>(b)     = *reinterpret_cast<float4*>(&Bs[kk][tn * 8]);
            *reinterpret_cast<float4*>(b + 4) = *reinterpret_cast<float4*>(&Bs[kk][tn * 8 + 4]);
#pragma unroll
            for (int i = 0; i < 8; i++)
#pragma unroll
                for (int j = 0; j < 8; j++) acc[i][j] += a[i] * b[j];
        }
        __syncthreads();
    }

#pragma unroll
    for (int i = 0; i < 8; i++) {
        int grow = row0 + tm * 8 + i;
        if (grow < NN) {
            *reinterpret_cast<float4*>(&g_h[grow * DD + tn * 8]) =
                *reinterpret_cast<float4*>(&acc[i][0]);
            *reinterpret_cast<float4*>(&g_h[grow * DD + tn * 8 + 4]) =
                *reinterpret_cast<float4*>(&acc[i][4]);
        }
    }
}

// ---------------- edge scatter: agg[dst] += norm[e] * h[src] ----------------
// one warp per edge; each lane: one float4 gather + one red.global.v4.f32
__device__ __forceinline__ void red_add_v4(float* p, float a, float b, float c, float d) {
    asm volatile("red.global.add.v4.f32 [%0], {%1, %2, %3, %4};"
                 :: "l"(p), "f"(a), "f"(b), "f"(c), "f"(d) : "memory");
}

// dst_sel: 0 -> g_agg, 1 -> out (param)
__global__ __launch_bounds__(256)
void scatter_kernel(const int* __restrict__ ei, float* __restrict__ out,
                    int dst_sel) {
    long long gtid = (long long)blockIdx.x * blockDim.x + threadIdx.x;
    int e = (int)(gtid >> 5);
    int lane = (int)(gtid & 31);
    if (e >= EE) return;
    float* __restrict__ agg = dst_sel ? out : g_agg;
    int src = ei[e];
    int dst = ei[EE + e];
    float nrm = g_norm[e];
    const float4 v = *reinterpret_cast<const float4*>(&g_h[src * DD + lane * 4]);
    red_add_v4(&agg[dst * DD + lane * 4], nrm * v.x, nrm * v.y, nrm * v.z, nrm * v.w);
}

// ---------------- epilogues (float4-vectorized, 32 threads per row) ----------------
// layer 1: g_agg = relu(g_agg + g_h*dinv^2 + b1)
__global__ __launch_bounds__(256)
void post1_kernel(const float* __restrict__ b) {
    int idx = blockIdx.x * blockDim.x + threadIdx.x;   // NN*32 threads
    if (idx >= NN * 32) return;
    int i = idx >> 5;
    int c4 = (idx & 31) * 4;
    float di = g_dinv[i];
    float d2 = di * di;
    float4 a = *reinterpret_cast<float4*>(&g_agg[i * DD + c4]);
    float4 h = *reinterpret_cast<float4*>(&g_h[i * DD + c4]);
    float4 bb = *reinterpret_cast<const float4*>(&b[c4]);
    a.x = fmaxf(a.x + h.x * d2 + bb.x, 0.f);
    a.y = fmaxf(a.y + h.y * d2 + bb.y, 0.f);
    a.z = fmaxf(a.z + h.z * d2 + bb.z, 0.f);
    a.w = fmaxf(a.w + h.w * d2 + bb.w, 0.f);
    *reinterpret_cast<float4*>(&g_agg[i * DD + c4]) = a;
}

// layer 2: out += g_h*dinv^2 + b2
__global__ __launch_bounds__(256)
void post2_kernel(const float* __restrict__ b, float* __restrict__ out) {
    int idx = blockIdx.x * blockDim.x + threadIdx.x;
    if (idx >= NN * 32) return;
    int i = idx >> 5;
    int c4 = (idx & 31) * 4;
    float di = g_dinv[i];
    float d2 = di * di;
    float4 o = *reinterpret_cast<float4*>(&out[i * DD + c4]);
    float4 h = *reinterpret_cast<float4*>(&g_h[i * DD + c4]);
    float4 bb = *reinterpret_cast<const float4*>(&b[c4]);
    o.x += h.x * d2 + bb.x;
    o.y += h.y * d2 + bb.y;
    o.z += h.z * d2 + bb.z;
    o.w += h.w * d2 + bb.w;
    *reinterpret_cast<float4*>(&out[i * DD + c4]) = o;
}

// ---------------- launch: kernel launches ONLY ----------------
extern "C" void kernel_launch(void* const* d_in, const int* in_sizes, int n_in,
                              void* d_out, int out_size) {
    const float* x  = (const float*)d_in[0];
    const int*   ei = (const int*)d_in[1];     // int32 (jax x64 disabled)
    const float* ew = (const float*)d_in[2];
    const float* W1 = (const float*)d_in[3];
    const float* b1 = (const float*)d_in[4];
    const float* W2 = (const float*)d_in[5];
    const float* b2 = (const float*)d_in[6];
    float* out = (float*)d_out;

    const int NB_N  = (NN + 255) / 256;
    const int NB_E  = (EE + 255) / 256;
    const int NB_P  = (NN * 32 + 255) / 256;
    const int NB_SC = (int)(((long long)EE * 32 + 255) / 256);
    const int NB_GM = (NN + BM - 1) / BM;

    init_kernel<<<1024, 256>>>(out);

    deg_kernel<<<NB_E, 256>>>(ei, ew);
    dinv_kernel<<<NB_N, 256>>>();
    norm_kernel<<<NB_E, 256>>>(ei, ew);

    // ---- layer 1 ----
    gemm_kernel<<<NB_GM, 256>>>(x, W1, 0);
    scatter_kernel<<<NB_SC, 256>>>(ei, out, 0);
    post1_kernel<<<NB_P, 256>>>(b1);

    // ---- layer 2 ----
    gemm_kernel<<<NB_GM, 256>>>(x, W2, 1);
    scatter_kernel<<<NB_SC, 256>>>(ei, out, 1);
    post2_kernel<<<NB_P, 256>>>(b2, out);
}

// round 8
// speedup vs baseline: 3.0274x; 1.3402x over previous
#include <cuda_runtime.h>
#include <cuda_bf16.h>

#define NN 50000
#define EE 600000
#define DD 128

#define SCAN_B 512
#define NSCAN ((NN + SCAN_B - 1) / SCAN_B)   // 98 blocks

// ---- scratch (device globals) ----
__device__ float g_dinv[NN];
__device__ int   g_cnt[NN];          // histogram, then fill cursor
__device__ int   g_off[NN];          // exclusive CSR offsets
__device__ int   g_bsum[NSCAN];      // scan block sums
__device__ int   g_esrc[EE];         // bucketed edge src
__device__ float g_enorm[EE];        // bucketed edge norm
__device__ float g_h[NN * DD];       // GEMM output (both layers)
__device__ float g_agg[NN * DD];     // layer-1 activation

// ---------------- CSR build ----------------
__global__ void zero_kernel() {
    int i = blockIdx.x * blockDim.x + threadIdx.x;
    if (i < NN) { g_cnt[i] = 0; g_dinv[i] = 0.0f; }
}

// deg[dst] += ew ; cnt[dst] += 1
__global__ void deg_hist_kernel(const int* __restrict__ ei,
                                const float* __restrict__ ew) {
    int e = blockIdx.x * blockDim.x + threadIdx.x;
    if (e < EE) {
        int dst = ei[EE + e];
        atomicAdd(&g_dinv[dst], ew[e]);
        atomicAdd(&g_cnt[dst], 1);
    }
}

__global__ void dinv_kernel() {
    int i = blockIdx.x * blockDim.x + threadIdx.x;
    if (i < NN) g_dinv[i] = rsqrtf(g_dinv[i] + 1.0f);
}

// per-block exclusive scan of g_cnt -> g_off ; block totals -> g_bsum
__global__ void scan1_kernel() {
    __shared__ int s[SCAN_B];
    int tid = threadIdx.x;
    int i = blockIdx.x * SCAN_B + tid;
    int v = (i < NN) ? g_cnt[i] : 0;
    s[tid] = v;
    __syncthreads();
#pragma unroll
    for (int d = 1; d < SCAN_B; d <<= 1) {
        int t = (tid >= d) ? s[tid - d] : 0;
        __syncthreads();
        s[tid] += t;
        __syncthreads();
    }
    if (i < NN) g_off[i] = s[tid] - v;   // exclusive within block
    if (tid == SCAN_B - 1) g_bsum[blockIdx.x] = s[tid];
}

// exclusive scan of the 98 block sums (single block)
__global__ void scan2_kernel() {
    __shared__ int s[128];
    int tid = threadIdx.x;
    int v = (tid < NSCAN) ? g_bsum[tid] : 0;
    s[tid] = v;
    __syncthreads();
#pragma unroll
    for (int d = 1; d < 128; d <<= 1) {
        int t = (tid >= d) ? s[tid - d] : 0;
        __syncthreads();
        s[tid] += t;
        __syncthreads();
    }
    if (tid < NSCAN) g_bsum[tid] = s[tid] - v;
}

// add block offsets; re-zero cnt for use as fill cursor
__global__ void scan3_kernel() {
    int i = blockIdx.x * blockDim.x + threadIdx.x;
    if (i < NN) {
        g_off[i] += g_bsum[i >> 9];
        g_cnt[i] = 0;
    }
}

// bucket edges by dst; fuse norm computation
__global__ void fill_kernel(const int* __restrict__ ei,
                            const float* __restrict__ ew) {
    int e = blockIdx.x * blockDim.x + threadIdx.x;
    if (e >= EE) return;
    int src = ei[e];
    int dst = ei[EE + e];
    float nrm = g_dinv[src] * ew[e] * g_dinv[dst];
    int slot = g_off[dst] + atomicAdd(&g_cnt[dst], 1);
    g_esrc[slot] = src;
    g_enorm[slot] = nrm;
}

// ---------------- GEMM: C[NN x 128] = A @ W ----------------
#define BM 128
#define BK 8

__global__ __launch_bounds__(256, 2)
void gemm_kernel(const float* __restrict__ x, const float* __restrict__ W,
                 int src_sel) {
    __shared__ float As[BK][BM];
    __shared__ float Bs[BK][DD];

    const float* __restrict__ A = src_sel ? g_agg : x;

    int tid = threadIdx.x;
    int row0 = blockIdx.x * BM;
    int tm = tid >> 4;
    int tn = tid & 15;

    float acc[8][8];
#pragma unroll
    for (int i = 0; i < 8; i++)
#pragma unroll
        for (int j = 0; j < 8; j++) acc[i][j] = 0.0f;

    int a_row = tid >> 1;
    int a_k4  = (tid & 1) * 4;
    int b_row = tid >> 5;
    int b_col = (tid & 31) * 4;

    for (int k0 = 0; k0 < DD; k0 += BK) {
        int grow = row0 + a_row;
        float4 av = make_float4(0.f, 0.f, 0.f, 0.f);
        if (grow < NN)
            av = *reinterpret_cast<const float4*>(&A[grow * DD + k0 + a_k4]);
        As[a_k4 + 0][a_row] = av.x;
        As[a_k4 + 1][a_row] = av.y;
        As[a_k4 + 2][a_row] = av.z;
        As[a_k4 + 3][a_row] = av.w;

        *reinterpret_cast<float4*>(&Bs[b_row][b_col]) =
            *reinterpret_cast<const float4*>(&W[(k0 + b_row) * DD + b_col]);
        __syncthreads();

#pragma unroll
        for (int kk = 0; kk < BK; kk++) {
            float a[8], b[8];
            *reinterpret_cast<float4*>(a)     = *reinterpret_cast<float4*>(&As[kk][tm * 8]);
            *reinterpret_cast<float4*>(a + 4) = *reinterpret_cast<float4*>(&As[kk][tm * 8 + 4]);
            *reinterpret_cast<float4*>(b)     = *reinterpret_cast<float4*>(&Bs[kk][tn * 8]);
            *reinterpret_cast<float4*>(b + 4) = *reinterpret_cast<float4*>(&Bs[kk][tn * 8 + 4]);
#pragma unroll
            for (int i = 0; i < 8; i++)
#pragma unroll
                for (int j = 0; j < 8; j++) acc[i][j] += a[i] * b[j];
        }
        __syncthreads();
    }

#pragma unroll
    for (int i = 0; i < 8; i++) {
        int grow = row0 + tm * 8 + i;
        if (grow < NN) {
            *reinterpret_cast<float4*>(&g_h[grow * DD + tn * 8]) =
                *reinterpret_cast<float4*>(&acc[i][0]);
            *reinterpret_cast<float4*>(&g_h[grow * DD + tn * 8 + 4]) =
                *reinterpret_cast<float4*>(&acc[i][4]);
        }
    }
}

// ---------------- aggregate: warp per node, no atomics ----------------
// result[node] = [relu]( sum_e nrm*h[src] + dinv^2*h[node] + b )
__global__ __launch_bounds__(256)
void agg_kernel(const float* __restrict__ b, float* __restrict__ outbuf,
                int dst_sel, int do_relu) {
    int gw = (blockIdx.x * blockDim.x + threadIdx.x) >> 5;  // warp id = node
    int lane = threadIdx.x & 31;
    if (gw >= NN) return;

    float* __restrict__ dstp = dst_sel ? outbuf : g_agg;
    const float4* __restrict__ h4 = reinterpret_cast<const float4*>(g_h);

    int beg = g_off[gw];
    int end = (gw + 1 < NN) ? g_off[gw + 1] : EE;

    float di = g_dinv[gw];
    float d2 = di * di;
    float4 self = h4[gw * 32 + lane];
    float4 bb = *reinterpret_cast<const float4*>(&b[lane * 4]);
    float4 acc;
    acc.x = d2 * self.x + bb.x;
    acc.y = d2 * self.y + bb.y;
    acc.z = d2 * self.z + bb.z;
    acc.w = d2 * self.w + bb.w;

    for (int e = beg; e < end; e++) {
        int src = g_esrc[e];        // uniform across warp -> broadcast
        float nrm = g_enorm[e];
        float4 v = h4[src * 32 + lane];
        acc.x += nrm * v.x;
        acc.y += nrm * v.y;
        acc.z += nrm * v.z;
        acc.w += nrm * v.w;
    }

    if (do_relu) {
        acc.x = fmaxf(acc.x, 0.f);
        acc.y = fmaxf(acc.y, 0.f);
        acc.z = fmaxf(acc.z, 0.f);
        acc.w = fmaxf(acc.w, 0.f);
    }
    *reinterpret_cast<float4*>(&dstp[gw * DD + lane * 4]) = acc;
}

// ---------------- launch: kernel launches ONLY ----------------
extern "C" void kernel_launch(void* const* d_in, const int* in_sizes, int n_in,
                              void* d_out, int out_size) {
    const float* x  = (const float*)d_in[0];
    const int*   ei = (const int*)d_in[1];     // int32 (jax x64 disabled)
    const float* ew = (const float*)d_in[2];
    const float* W1 = (const float*)d_in[3];
    const float* b1 = (const float*)d_in[4];
    const float* W2 = (const float*)d_in[5];
    const float* b2 = (const float*)d_in[6];
    float* out = (float*)d_out;

    const int NB_N  = (NN + 255) / 256;
    const int NB_E  = (EE + 255) / 256;
    const int NB_GM = (NN + BM - 1) / BM;
    const int NB_AG = (NN * 32 + 255) / 256;

    // ---- CSR build (once per launch, in-graph) ----
    zero_kernel<<<NB_N, 256>>>();
    deg_hist_kernel<<<NB_E, 256>>>(ei, ew);
    dinv_kernel<<<NB_N, 256>>>();
    scan1_kernel<<<NSCAN, SCAN_B>>>();
    scan2_kernel<<<1, 128>>>();
    scan3_kernel<<<NB_N, 256>>>();
    fill_kernel<<<NB_E, 256>>>(ei, ew);

    // ---- layer 1 ----
    gemm_kernel<<<NB_GM, 256>>>(x, W1, 0);
    agg_kernel<<<NB_AG, 256>>>(b1, out, 0, 1);

    // ---- layer 2 ----
    gemm_kernel<<<NB_GM, 256>>>(x, W2, 1);
    agg_kernel<<<NB_AG, 256>>>(b2, out, 1, 0);
}

// round 12
// speedup vs baseline: 4.4140x; 1.4580x over previous
#include <cuda_runtime.h>
#include <cuda_bf16.h>
#include <cstdint>

#define NN 50000
#define EE 600000
#define DD 128

#define SCAN_B 512
#define NSCAN ((NN + SCAN_B - 1) / SCAN_B)   // 98 blocks

// ---- scratch (device globals) ----
__device__ float g_dinv[NN];
__device__ int   g_cnt[NN];
__device__ int   g_off[NN];
__device__ int   g_bsum[NSCAN];
__device__ int   g_esrc[EE];
__device__ float g_enorm[EE];
__device__ float g_h[NN * DD];                    // GEMM output (both layers)
__device__ float g_agg[NN * DD];                  // layer-1 activation
__device__ __nv_bfloat16 g_wimg[2][2][DD * DD];   // [layer][hi/lo] W^T as [n][k]

// ================= CSR build =================
__global__ void zero_kernel() {
    int i = blockIdx.x * blockDim.x + threadIdx.x;
    if (i < NN) { g_cnt[i] = 0; g_dinv[i] = 0.0f; }
}
__global__ void deg_hist_kernel(const int* __restrict__ ei, const float* __restrict__ ew) {
    int e = blockIdx.x * blockDim.x + threadIdx.x;
    if (e < EE) {
        int dst = ei[EE + e];
        atomicAdd(&g_dinv[dst], ew[e]);
        atomicAdd(&g_cnt[dst], 1);
    }
}
__global__ void dinv_kernel() {
    int i = blockIdx.x * blockDim.x + threadIdx.x;
    if (i < NN) g_dinv[i] = rsqrtf(g_dinv[i] + 1.0f);
}
__global__ void scan1_kernel() {
    __shared__ int s[SCAN_B];
    int tid = threadIdx.x;
    int i = blockIdx.x * SCAN_B + tid;
    int v = (i < NN) ? g_cnt[i] : 0;
    s[tid] = v;
    __syncthreads();
#pragma unroll
    for (int d = 1; d < SCAN_B; d <<= 1) {
        int t = (tid >= d) ? s[tid - d] : 0;
        __syncthreads();
        s[tid] += t;
        __syncthreads();
    }
    if (i < NN) g_off[i] = s[tid] - v;
    if (tid == SCAN_B - 1) g_bsum[blockIdx.x] = s[tid];
}
__global__ void scan2_kernel() {
    __shared__ int s[128];
    int tid = threadIdx.x;
    int v = (tid < NSCAN) ? g_bsum[tid] : 0;
    s[tid] = v;
    __syncthreads();
#pragma unroll
    for (int d = 1; d < 128; d <<= 1) {
        int t = (tid >= d) ? s[tid - d] : 0;
        __syncthreads();
        s[tid] += t;
        __syncthreads();
    }
    if (tid < NSCAN) g_bsum[tid] = s[tid] - v;
}
__global__ void scan3_kernel() {
    int i = blockIdx.x * blockDim.x + threadIdx.x;
    if (i < NN) { g_off[i] += g_bsum[i >> 9]; g_cnt[i] = 0; }
}
__global__ void fill_kernel(const int* __restrict__ ei, const float* __restrict__ ew) {
    int e = blockIdx.x * blockDim.x + threadIdx.x;
    if (e >= EE) return;
    int src = ei[e];
    int dst = ei[EE + e];
    float nrm = g_dinv[src] * ew[e] * g_dinv[dst];
    int slot = g_off[dst] + atomicAdd(&g_cnt[dst], 1);
    g_esrc[slot] = src;
    g_enorm[slot] = nrm;
}

// ============ W pre-conversion: fp32 -> split bf16, W^T [n][k] ============
__global__ void convw_kernel(const float* __restrict__ W1, const float* __restrict__ W2) {
    int idx = blockIdx.x * blockDim.x + threadIdx.x;
    if (idx >= 2 * DD * DD) return;
    int layer = idx >> 14;
    int kn = idx & (DD * DD - 1);
    int k = kn >> 7, n = kn & 127;
    const float* W = layer ? W2 : W1;
    float v = W[k * DD + n];
    __nv_bfloat16 hi = __float2bfloat16(v);
    __nv_bfloat16 lo = __float2bfloat16(v - __bfloat162float(hi));
    g_wimg[layer][0][n * DD + k] = hi;
    g_wimg[layer][1][n * DD + k] = lo;
}

// ============ GEMM via mma.sync bf16 (3-pass split): g_h = A @ W ============
// CTA: 128 rows x 128 cols, 8 warps, warp = 16 rows x 128 cols.
// smem images padded to 68 uint32 words/row -> conflict-free frag loads.
#define PADW 68
#define IMG_W (128 * PADW)                 // words per image
#define GEMM_SMEM (4 * IMG_W * 4)          // 139264 bytes

__device__ __forceinline__ void mma_bf16(float* c, uint32_t a0, uint32_t a1,
                                         uint32_t a2, uint32_t a3,
                                         uint32_t b0, uint32_t b1) {
    asm volatile(
        "mma.sync.aligned.m16n8k16.row.col.f32.bf16.bf16.f32 "
        "{%0,%1,%2,%3}, {%4,%5,%6,%7}, {%8,%9}, {%0,%1,%2,%3};"
        : "+f"(c[0]), "+f"(c[1]), "+f"(c[2]), "+f"(c[3])
        : "r"(a0), "r"(a1), "r"(a2), "r"(a3), "r"(b0), "r"(b1));
}

__global__ void __launch_bounds__(256, 1)
gemm_mma_kernel(const float* __restrict__ x, int layer) {
    extern __shared__ uint32_t sm[];
    uint32_t* Ahi = sm;
    uint32_t* Alo = Ahi + IMG_W;
    uint32_t* Bhi = Alo + IMG_W;           // W^T [n][k]
    uint32_t* Blo = Bhi + IMG_W;

    const float* __restrict__ A = layer ? g_agg : x;
    int tid = threadIdx.x;

    // repack W images global [n][64 words] -> smem [n][PADW]
    {
        const uint32_t* wh = reinterpret_cast<const uint32_t*>(g_wimg[layer][0]);
        const uint32_t* wl = reinterpret_cast<const uint32_t*>(g_wimg[layer][1]);
#pragma unroll
        for (int t = 0; t < 32; t++) {     // 8192 words
            int idx = tid + t * 256;
            int n = idx >> 6, k2 = idx & 63;
            Bhi[n * PADW + k2] = wh[idx];
            Blo[n * PADW + k2] = wl[idx];
        }
    }
    // convert A tile: thread = (row, half-row of 64 cols)
    {
        int row = tid >> 1, hf = tid & 1;
        int grow = blockIdx.x * 128 + row;
        bool ok = grow < NN;
        const float4* ar = reinterpret_cast<const float4*>(A + (size_t)(ok ? grow : 0) * DD) + hf * 16;
        uint32_t* dh = Ahi + row * PADW + hf * 32;
        uint32_t* dl = Alo + row * PADW + hf * 32;
#pragma unroll
        for (int j = 0; j < 16; j++) {
            float4 v = ok ? ar[j] : make_float4(0.f, 0.f, 0.f, 0.f);
            __nv_bfloat162 h01 = __floats2bfloat162_rn(v.x, v.y);
            __nv_bfloat162 h23 = __floats2bfloat162_rn(v.z, v.w);
            __nv_bfloat162 l01 = __floats2bfloat162_rn(v.x - __low2float(h01), v.y - __high2float(h01));
            __nv_bfloat162 l23 = __floats2bfloat162_rn(v.z - __low2float(h23), v.w - __high2float(h23));
            dh[2 * j]     = *reinterpret_cast<uint32_t*>(&h01);
            dh[2 * j + 1] = *reinterpret_cast<uint32_t*>(&h23);
            dl[2 * j]     = *reinterpret_cast<uint32_t*>(&l01);
            dl[2 * j + 1] = *reinterpret_cast<uint32_t*>(&l23);
        }
    }
    __syncthreads();

    int w = tid >> 5, l = tid & 31;
    int g = l >> 2, q = l & 3;

    float acc[16][4];
#pragma unroll
    for (int nt = 0; nt < 16; nt++)
#pragma unroll
        for (int i = 0; i < 4; i++) acc[nt][i] = 0.0f;

    int arow = w * 16 + g;

    for (int kt = 0; kt < 8; kt++) {
        int kw = kt * 8 + q;
        uint32_t a0h = Ahi[arow * PADW + kw];
        uint32_t a1h = Ahi[(arow + 8) * PADW + kw];
        uint32_t a2h = Ahi[arow * PADW + kw + 4];
        uint32_t a3h = Ahi[(arow + 8) * PADW + kw + 4];
        uint32_t a0l = Alo[arow * PADW + kw];
        uint32_t a1l = Alo[(arow + 8) * PADW + kw];
        uint32_t a2l = Alo[arow * PADW + kw + 4];
        uint32_t a3l = Alo[(arow + 8) * PADW + kw + 4];

        uint32_t bh[16][2];
#pragma unroll
        for (int nt = 0; nt < 16; nt++) {
            int n = nt * 8 + g;
            bh[nt][0] = Bhi[n * PADW + kw];
            bh[nt][1] = Bhi[n * PADW + kw + 4];
            mma_bf16(acc[nt], a0h, a1h, a2h, a3h, bh[nt][0], bh[nt][1]);
        }
#pragma unroll
        for (int nt = 0; nt < 16; nt++)
            mma_bf16(acc[nt], a0l, a1l, a2l, a3l, bh[nt][0], bh[nt][1]);
#pragma unroll
        for (int nt = 0; nt < 16; nt++) {
            int n = nt * 8 + g;
            uint32_t b0 = Blo[n * PADW + kw];
            uint32_t b1 = Blo[n * PADW + kw + 4];
            mma_bf16(acc[nt], a0h, a1h, a2h, a3h, b0, b1);
        }
    }

    // store: thread owns rows (r0, r0+8), cols nt*8 + q*2 (+1)
    int r0 = blockIdx.x * 128 + w * 16 + g;
#pragma unroll
    for (int nt = 0; nt < 16; nt++) {
        int c = nt * 8 + q * 2;
        if (r0 < NN)
            *reinterpret_cast<float2*>(&g_h[(size_t)r0 * DD + c]) =
                make_float2(acc[nt][0], acc[nt][1]);
        if (r0 + 8 < NN)
            *reinterpret_cast<float2*>(&g_h[(size_t)(r0 + 8) * DD + c]) =
                make_float2(acc[nt][2], acc[nt][3]);
    }
}

// ================= aggregate: warp per node, no atomics =================
__global__ __launch_bounds__(256)
void agg_kernel(const float* __restrict__ b, float* __restrict__ outbuf,
                int dst_sel, int do_relu) {
    int gw = (blockIdx.x * blockDim.x + threadIdx.x) >> 5;
    int lane = threadIdx.x & 31;
    if (gw >= NN) return;

    float* __restrict__ dstp = dst_sel ? outbuf : g_agg;
    const float4* __restrict__ h4 = reinterpret_cast<const float4*>(g_h);

    int beg = g_off[gw];
    int end = (gw + 1 < NN) ? g_off[gw + 1] : EE;

    float di = g_dinv[gw];
    float d2 = di * di;
    float4 self = h4[gw * 32 + lane];
    float4 bb = *reinterpret_cast<const float4*>(&b[lane * 4]);
    float4 acc;
    acc.x = d2 * self.x + bb.x;
    acc.y = d2 * self.y + bb.y;
    acc.z = d2 * self.z + bb.z;
    acc.w = d2 * self.w + bb.w;

    for (int e = beg; e < end; e++) {
        int src = g_esrc[e];
        float nrm = g_enorm[e];
        float4 v = h4[src * 32 + lane];
        acc.x += nrm * v.x;
        acc.y += nrm * v.y;
        acc.z += nrm * v.z;
        acc.w += nrm * v.w;
    }

    if (do_relu) {
        acc.x = fmaxf(acc.x, 0.f);
        acc.y = fmaxf(acc.y, 0.f);
        acc.z = fmaxf(acc.z, 0.f);
        acc.w = fmaxf(acc.w, 0.f);
    }
    *reinterpret_cast<float4*>(&dstp[gw * DD + lane * 4]) = acc;
}

// ================= launch =================
extern "C" void kernel_launch(void* const* d_in, const int* in_sizes, int n_in,
                              void* d_out, int out_size) {
    const float* x  = (const float*)d_in[0];
    const int*   ei = (const int*)d_in[1];     // int32 (jax x64 disabled)
    const float* ew = (const float*)d_in[2];
    const float* b1 = (const float*)d_in[4];
    const float* W1 = (const float*)d_in[3];
    const float* W2 = (const float*)d_in[5];
    const float* b2 = (const float*)d_in[6];
    float* out = (float*)d_out;

    // idempotent attribute set; done once (not a work guard — launched work
    // below is identical on every call)
    static bool attr_done = false;
    if (!attr_done) {
        cudaFuncSetAttribute(gemm_mma_kernel,
                             cudaFuncAttributeMaxDynamicSharedMemorySize, GEMM_SMEM);
        attr_done = true;
    }

    const int NB_N  = (NN + 255) / 256;
    const int NB_E  = (EE + 255) / 256;
    const int NB_AG = (NN * 32 + 255) / 256;
    const int NB_GM = (NN + 127) / 128;        // 391 tiles

    // ---- CSR build + W conversion ----
    zero_kernel<<<NB_N, 256>>>();
    convw_kernel<<<(2 * DD * DD + 255) / 256, 256>>>(W1, W2);
    deg_hist_kernel<<<NB_E, 256>>>(ei, ew);
    dinv_kernel<<<NB_N, 256>>>();
    scan1_kernel<<<NSCAN, SCAN_B>>>();
    scan2_kernel<<<1, 128>>>();
    scan3_kernel<<<NB_N, 256>>>();
    fill_kernel<<<NB_E, 256>>>(ei, ew);

    // ---- layer 1 ----
    gemm_mma_kernel<<<NB_GM, 256, GEMM_SMEM>>>(x, 0);
    agg_kernel<<<NB_AG, 256>>>(b1, out, 0, 1);

    // ---- layer 2 ----
    gemm_mma_kernel<<<NB_GM, 256, GEMM_SMEM>>>(x, 1);
    agg_kernel<<<NB_AG, 256>>>(b2, out, 1, 0);
}

// round 14
// speedup vs baseline: 4.5588x; 1.0328x over previous
#include <cuda_runtime.h>
#include <cuda_bf16.h>
#include <cstdint>

#define NN 50000
#define EE 600000
#define DD 128

#define SCAN_B 512
#define NSCAN ((NN + SCAN_B - 1) / SCAN_B)   // 98 blocks

// ---- scratch (device globals) ----
__device__ float g_dinv[NN];
__device__ int   g_cnt[NN];
__device__ int   g_off[NN];      // per-block exclusive scan (block offset added by consumers)
__device__ int   g_bsum[NSCAN];  // exclusive scan of block totals
__device__ int   g_esrc[EE];
__device__ float g_enorm[EE];
__device__ float g_h[NN * DD];                    // GEMM output (both layers)
__device__ float g_agg[NN * DD];                  // layer-1 activation
__device__ __nv_bfloat16 g_wimg[2][2][DD * DD];   // [layer][hi/lo] W^T as [n][k]

// ========== fused init: zero cnt/dinv + W split-bf16 conversion ==========
__global__ void initconv_kernel(const float* __restrict__ W1, const float* __restrict__ W2) {
    int i = blockIdx.x * blockDim.x + threadIdx.x;
    if (i < NN) { g_cnt[i] = 0; g_dinv[i] = 0.0f; }
    if (i < 2 * DD * DD) {
        int layer = i >> 14;
        int kn = i & (DD * DD - 1);
        int k = kn >> 7, n = kn & 127;
        const float* W = layer ? W2 : W1;
        float v = W[k * DD + n];
        __nv_bfloat16 hi = __float2bfloat16(v);
        __nv_bfloat16 lo = __float2bfloat16(v - __bfloat162float(hi));
        g_wimg[layer][0][n * DD + k] = hi;
        g_wimg[layer][1][n * DD + k] = lo;
    }
}

__global__ void deg_hist_kernel(const int* __restrict__ ei, const float* __restrict__ ew) {
    int e = blockIdx.x * blockDim.x + threadIdx.x;
    if (e < EE) {
        int dst = ei[EE + e];
        atomicAdd(&g_dinv[dst], ew[e]);
        atomicAdd(&g_cnt[dst], 1);
    }
}

// per-block exclusive scan of g_cnt -> g_off ; block totals -> g_bsum
// fused: dinv finalize (rsqrt) + cnt reset (cursor for fill)
__global__ void scan1_kernel() {
    __shared__ int s[SCAN_B];
    int tid = threadIdx.x;
    int i = blockIdx.x * SCAN_B + tid;
    int v = (i < NN) ? g_cnt[i] : 0;
    s[tid] = v;
    __syncthreads();
#pragma unroll
    for (int d = 1; d < SCAN_B; d <<= 1) {
        int t = (tid >= d) ? s[tid - d] : 0;
        __syncthreads();
        s[tid] += t;
        __syncthreads();
    }
    if (i < NN) {
        g_off[i] = s[tid] - v;
        g_cnt[i] = 0;
        g_dinv[i] = rsqrtf(g_dinv[i] + 1.0f);
    }
    if (tid == SCAN_B - 1) g_bsum[blockIdx.x] = s[tid];
}

// exclusive scan of the 98 block sums (single block)
__global__ void scan2_kernel() {
    __shared__ int s[128];
    int tid = threadIdx.x;
    int v = (tid < NSCAN) ? g_bsum[tid] : 0;
    s[tid] = v;
    __syncthreads();
#pragma unroll
    for (int d = 1; d < 128; d <<= 1) {
        int t = (tid >= d) ? s[tid - d] : 0;
        __syncthreads();
        s[tid] += t;
        __syncthreads();
    }
    if (tid < NSCAN) g_bsum[tid] = s[tid] - v;
}

// bucket edges by dst (block offset resolved inline); fuse norm computation
__global__ void fill_kernel(const int* __restrict__ ei, const float* __restrict__ ew) {
    int e = blockIdx.x * blockDim.x + threadIdx.x;
    if (e >= EE) return;
    int src = ei[e];
    int dst = ei[EE + e];
    float nrm = g_dinv[src] * ew[e] * g_dinv[dst];
    int slot = g_off[dst] + g_bsum[dst >> 9] + atomicAdd(&g_cnt[dst], 1);
    g_esrc[slot] = src;
    g_enorm[slot] = nrm;
}

// ============ GEMM via mma.sync bf16 (3-pass split): g_h = A @ W ============
#define PADW 68
#define IMG_W (128 * PADW)
#define GEMM_SMEM (4 * IMG_W * 4)          // 139264 bytes

__device__ __forceinline__ void mma_bf16(float* c, uint32_t a0, uint32_t a1,
                                         uint32_t a2, uint32_t a3,
                                         uint32_t b0, uint32_t b1) {
    asm volatile(
        "mma.sync.aligned.m16n8k16.row.col.f32.bf16.bf16.f32 "
        "{%0,%1,%2,%3}, {%4,%5,%6,%7}, {%8,%9}, {%0,%1,%2,%3};"
        : "+f"(c[0]), "+f"(c[1]), "+f"(c[2]), "+f"(c[3])
        : "r"(a0), "r"(a1), "r"(a2), "r"(a3), "r"(b0), "r"(b1));
}

__global__ void __launch_bounds__(256, 1)
gemm_mma_kernel(const float* __restrict__ x, int layer) {
    extern __shared__ uint32_t sm[];
    uint32_t* Ahi = sm;
    uint32_t* Alo = Ahi + IMG_W;
    uint32_t* Bhi = Alo + IMG_W;
    uint32_t* Blo = Bhi + IMG_W;

    const float* __restrict__ A = layer ? g_agg : x;
    int tid = threadIdx.x;

    {
        const uint32_t* wh = reinterpret_cast<const uint32_t*>(g_wimg[layer][0]);
        const uint32_t* wl = reinterpret_cast<const uint32_t*>(g_wimg[layer][1]);
#pragma unroll
        for (int t = 0; t < 32; t++) {
            int idx = tid + t * 256;
            int n = idx >> 6, k2 = idx & 63;
            Bhi[n * PADW + k2] = wh[idx];
            Blo[n * PADW + k2] = wl[idx];
        }
    }
    {
        int row = tid >> 1, hf = tid & 1;
        int grow = blockIdx.x * 128 + row;
        bool ok = grow < NN;
        const float4* ar = reinterpret_cast<const float4*>(A + (size_t)(ok ? grow : 0) * DD) + hf * 16;
        uint32_t* dh = Ahi + row * PADW + hf * 32;
        uint32_t* dl = Alo + row * PADW + hf * 32;
#pragma unroll
        for (int j = 0; j < 16; j++) {
            float4 v = ok ? ar[j] : make_float4(0.f, 0.f, 0.f, 0.f);
            __nv_bfloat162 h01 = __floats2bfloat162_rn(v.x, v.y);
            __nv_bfloat162 h23 = __floats2bfloat162_rn(v.z, v.w);
            __nv_bfloat162 l01 = __floats2bfloat162_rn(v.x - __low2float(h01), v.y - __high2float(h01));
            __nv_bfloat162 l23 = __floats2bfloat162_rn(v.z - __low2float(h23), v.w - __high2float(h23));
            dh[2 * j]     = *reinterpret_cast<uint32_t*>(&h01);
            dh[2 * j + 1] = *reinterpret_cast<uint32_t*>(&h23);
            dl[2 * j]     = *reinterpret_cast<uint32_t*>(&l01);
            dl[2 * j + 1] = *reinterpret_cast<uint32_t*>(&l23);
        }
    }
    __syncthreads();

    int w = tid >> 5, l = tid & 31;
    int g = l >> 2, q = l & 3;

    float acc[16][4];
#pragma unroll
    for (int nt = 0; nt < 16; nt++)
#pragma unroll
        for (int i = 0; i < 4; i++) acc[nt][i] = 0.0f;

    int arow = w * 16 + g;

    for (int kt = 0; kt < 8; kt++) {
        int kw = kt * 8 + q;
        uint32_t a0h = Ahi[arow * PADW + kw];
        uint32_t a1h = Ahi[(arow + 8) * PADW + kw];
        uint32_t a2h = Ahi[arow * PADW + kw + 4];
        uint32_t a3h = Ahi[(arow + 8) * PADW + kw + 4];
        uint32_t a0l = Alo[arow * PADW + kw];
        uint32_t a1l = Alo[(arow + 8) * PADW + kw];
        uint32_t a2l = Alo[arow * PADW + kw + 4];
        uint32_t a3l = Alo[(arow + 8) * PADW + kw + 4];

        uint32_t bh[16][2];
#pragma unroll
        for (int nt = 0; nt < 16; nt++) {
            int n = nt * 8 + g;
            bh[nt][0] = Bhi[n * PADW + kw];
            bh[nt][1] = Bhi[n * PADW + kw + 4];
            mma_bf16(acc[nt], a0h, a1h, a2h, a3h, bh[nt][0], bh[nt][1]);
        }
#pragma unroll
        for (int nt = 0; nt < 16; nt++)
            mma_bf16(acc[nt], a0l, a1l, a2l, a3l, bh[nt][0], bh[nt][1]);
#pragma unroll
        for (int nt = 0; nt < 16; nt++) {
            int n = nt * 8 + g;
            uint32_t b0 = Blo[n * PADW + kw];
            uint32_t b1 = Blo[n * PADW + kw + 4];
            mma_bf16(acc[nt], a0h, a1h, a2h, a3h, b0, b1);
        }
    }

    int r0 = blockIdx.x * 128 + w * 16 + g;
#pragma unroll
    for (int nt = 0; nt < 16; nt++) {
        int c = nt * 8 + q * 2;
        if (r0 < NN)
            *reinterpret_cast<float2*>(&g_h[(size_t)r0 * DD + c]) =
                make_float2(acc[nt][0], acc[nt][1]);
        if (r0 + 8 < NN)
            *reinterpret_cast<float2*>(&g_h[(size_t)(r0 + 8) * DD + c]) =
                make_float2(acc[nt][2], acc[nt][3]);
    }
}

// ================= aggregate: warp per node, no atomics =================
__global__ __launch_bounds__(256)
void agg_kernel(const float* __restrict__ b, float* __restrict__ outbuf,
                int dst_sel, int do_relu) {
    int gw = (blockIdx.x * blockDim.x + threadIdx.x) >> 5;
    int lane = threadIdx.x & 31;
    if (gw >= NN) return;

    float* __restrict__ dstp = dst_sel ? outbuf : g_agg;
    const float4* __restrict__ h4 = reinterpret_cast<const float4*>(g_h);

    int beg = g_off[gw] + g_bsum[gw >> 9];
    int end = (gw + 1 < NN) ? (g_off[gw + 1] + g_bsum[(gw + 1) >> 9]) : EE;

    float di = g_dinv[gw];
    float d2 = di * di;
    float4 self = h4[gw * 32 + lane];
    float4 bb = *reinterpret_cast<const float4*>(&b[lane * 4]);
    float4 acc;
    acc.x = d2 * self.x + bb.x;
    acc.y = d2 * self.y + bb.y;
    acc.z = d2 * self.z + bb.z;
    acc.w = d2 * self.w + bb.w;

    for (int e = beg; e < end; e++) {
        int src = g_esrc[e];
        float nrm = g_enorm[e];
        float4 v = h4[src * 32 + lane];
        acc.x += nrm * v.x;
        acc.y += nrm * v.y;
        acc.z += nrm * v.z;
        acc.w += nrm * v.w;
    }

    if (do_relu) {
        acc.x = fmaxf(acc.x, 0.f);
        acc.y = fmaxf(acc.y, 0.f);
        acc.z = fmaxf(acc.z, 0.f);
        acc.w = fmaxf(acc.w, 0.f);
    }
    *reinterpret_cast<float4*>(&dstp[gw * DD + lane * 4]) = acc;
}

// ================= launch =================
extern "C" void kernel_launch(void* const* d_in, const int* in_sizes, int n_in,
                              void* d_out, int out_size) {
    const float* x  = (const float*)d_in[0];
    const int*   ei = (const int*)d_in[1];     // int32 (jax x64 disabled)
    const float* ew = (const float*)d_in[2];
    const float* W1 = (const float*)d_in[3];
    const float* b1 = (const float*)d_in[4];
    const float* W2 = (const float*)d_in[5];
    const float* b2 = (const float*)d_in[6];
    float* out = (float*)d_out;

    static bool attr_done = false;
    if (!attr_done) {
        cudaFuncSetAttribute(gemm_mma_kernel,
                             cudaFuncAttributeMaxDynamicSharedMemorySize, GEMM_SMEM);
        attr_done = true;
    }

    const int NB_N  = (NN + 255) / 256;        // covers 2*DD*DD = 32768 too
    const int NB_E  = (EE + 255) / 256;
    const int NB_AG = (NN * 32 + 255) / 256;
    const int NB_GM = (NN + 127) / 128;        // 391 tiles

    // ---- prologue: CSR build + W conversion (5 launches) ----
    initconv_kernel<<<NB_N, 256>>>(W1, W2);
    deg_hist_kernel<<<NB_E, 256>>>(ei, ew);
    scan1_kernel<<<NSCAN, SCAN_B>>>();
    scan2_kernel<<<1, 128>>>();
    fill_kernel<<<NB_E, 256>>>(ei, ew);

    // ---- layer 1 ----
    gemm_mma_kernel<<<NB_GM, 256, GEMM_SMEM>>>(x, 0);
    agg_kernel<<<NB_AG, 256>>>(b1, out, 0, 1);

    // ---- layer 2 ----
    gemm_mma_kernel<<<NB_GM, 256, GEMM_SMEM>>>(x, 1);
    agg_kernel<<<NB_AG, 256>>>(b2, out, 1, 0);
}

// round 15
// speedup vs baseline: 4.8467x; 1.0632x over previous
#include <cuda_runtime.h>
#include <cuda_bf16.h>
#include <cstdint>

#define NN 50000
#define EE 600000
#define DD 128

#define SCAN_B 512
#define NSCAN ((NN + SCAN_B - 1) / SCAN_B)   // 98 blocks

// ---- scratch (device globals) ----
__device__ float g_dinv[NN];
__device__ int   g_cnt[NN];
__device__ int   g_off[NN];      // per-block exclusive scan (block offset added by consumers)
__device__ int   g_bsum[NSCAN];  // block totals, then exclusive scan of them
__device__ int   g_ticket;       // last-block detection for fused scan
__device__ int   g_esrc[EE];
__device__ float g_enorm[EE];
__device__ float g_h[NN * DD];                    // GEMM output (both layers)
__device__ float g_agg[NN * DD];                  // layer-1 activation
__device__ __nv_bfloat16 g_wimg[2][2][DD * DD];   // [layer][hi/lo] W^T as [n][k]

// ========== fused init: zero cnt/dinv/ticket + W split-bf16 conversion ==========
__global__ void initconv_kernel(const float* __restrict__ W1, const float* __restrict__ W2) {
    int i = blockIdx.x * blockDim.x + threadIdx.x;
    if (i == 0) g_ticket = 0;
    if (i < NN) { g_cnt[i] = 0; g_dinv[i] = 0.0f; }
    if (i < 2 * DD * DD) {
        int layer = i >> 14;
        int kn = i & (DD * DD - 1);
        int k = kn >> 7, n = kn & 127;
        const float* W = layer ? W2 : W1;
        float v = W[k * DD + n];
        __nv_bfloat16 hi = __float2bfloat16(v);
        __nv_bfloat16 lo = __float2bfloat16(v - __bfloat162float(hi));
        g_wimg[layer][0][n * DD + k] = hi;
        g_wimg[layer][1][n * DD + k] = lo;
    }
}

__global__ void deg_hist_kernel(const int* __restrict__ ei, const float* __restrict__ ew) {
    int e = blockIdx.x * blockDim.x + threadIdx.x;
    if (e < EE) {
        int dst = ei[EE + e];
        atomicAdd(&g_dinv[dst], ew[e]);
        atomicAdd(&g_cnt[dst], 1);
    }
}

// per-block exclusive scan of g_cnt -> g_off ; block totals -> g_bsum.
// fused: dinv finalize + cnt reset + (last block) exclusive scan of g_bsum.
__global__ void scan1_kernel() {
    __shared__ int s[SCAN_B];
    __shared__ int isLast;
    int tid = threadIdx.x;
    int i = blockIdx.x * SCAN_B + tid;
    int v = (i < NN) ? g_cnt[i] : 0;
    s[tid] = v;
    __syncthreads();
#pragma unroll
    for (int d = 1; d < SCAN_B; d <<= 1) {
        int t = (tid >= d) ? s[tid - d] : 0;
        __syncthreads();
        s[tid] += t;
        __syncthreads();
    }
    if (i < NN) {
        g_off[i] = s[tid] - v;
        g_cnt[i] = 0;
        g_dinv[i] = rsqrtf(g_dinv[i] + 1.0f);
    }
    if (tid == SCAN_B - 1) g_bsum[blockIdx.x] = s[tid];

    // last-block: exclusive scan of the NSCAN block sums (replaces scan2 launch)
    __threadfence();
    if (tid == 0) isLast = (atomicAdd(&g_ticket, 1) == gridDim.x - 1);
    __syncthreads();
    if (isLast) {
        int bv = (tid < NSCAN) ? g_bsum[tid] : 0;
        s[tid] = (tid < 128) ? bv : 0;
        __syncthreads();
#pragma unroll
        for (int d = 1; d < 128; d <<= 1) {
            int t = (tid >= d && tid < 128) ? s[tid - d] : 0;
            __syncthreads();
            if (tid < 128) s[tid] += t;
            __syncthreads();
        }
        if (tid < NSCAN) g_bsum[tid] = s[tid] - bv;
        if (tid == 0) g_ticket = 0;   // reset for next launch
    }
}

// bucket edges by dst (block offset resolved inline); fuse norm computation
__global__ void fill_kernel(const int* __restrict__ ei, const float* __restrict__ ew) {
    int e = blockIdx.x * blockDim.x + threadIdx.x;
    if (e >= EE) return;
    int src = ei[e];
    int dst = ei[EE + e];
    float nrm = g_dinv[src] * ew[e] * g_dinv[dst];
    int slot = g_off[dst] + g_bsum[dst >> 9] + atomicAdd(&g_cnt[dst], 1);
    g_esrc[slot] = src;
    g_enorm[slot] = nrm;
}

// ============ GEMM via mma.sync bf16 (3-pass split): g_h = A @ W ============
#define PADW 68
#define IMG_W (128 * PADW)
#define GEMM_SMEM (4 * IMG_W * 4)          // 139264 bytes

__device__ __forceinline__ void mma_bf16(float* c, uint32_t a0, uint32_t a1,
                                         uint32_t a2, uint32_t a3,
                                         uint32_t b0, uint32_t b1) {
    asm volatile(
        "mma.sync.aligned.m16n8k16.row.col.f32.bf16.bf16.f32 "
        "{%0,%1,%2,%3}, {%4,%5,%6,%7}, {%8,%9}, {%0,%1,%2,%3};"
        : "+f"(c[0]), "+f"(c[1]), "+f"(c[2]), "+f"(c[3])
        : "r"(a0), "r"(a1), "r"(a2), "r"(a3), "r"(b0), "r"(b1));
}

__global__ void __launch_bounds__(256, 1)
gemm_mma_kernel(const float* __restrict__ x, int layer) {
    extern __shared__ uint32_t sm[];
    uint32_t* Ahi = sm;
    uint32_t* Alo = Ahi + IMG_W;
    uint32_t* Bhi = Alo + IMG_W;
    uint32_t* Blo = Bhi + IMG_W;

    const float* __restrict__ A = layer ? g_agg : x;
    int tid = threadIdx.x;

    {
        const uint32_t* wh = reinterpret_cast<const uint32_t*>(g_wimg[layer][0]);
        const uint32_t* wl = reinterpret_cast<const uint32_t*>(g_wimg[layer][1]);
#pragma unroll
        for (int t = 0; t < 32; t++) {
            int idx = tid + t * 256;
            int n = idx >> 6, k2 = idx & 63;
            Bhi[n * PADW + k2] = wh[idx];
            Blo[n * PADW + k2] = wl[idx];
        }
    }
    {
        int row = tid >> 1, hf = tid & 1;
        int grow = blockIdx.x * 128 + row;
        bool ok = grow < NN;
        const float4* ar = reinterpret_cast<const float4*>(A + (size_t)(ok ? grow : 0) * DD) + hf * 16;
        uint32_t* dh = Ahi + row * PADW + hf * 32;
        uint32_t* dl = Alo + row * PADW + hf * 32;
#pragma unroll
        for (int j = 0; j < 16; j++) {
            float4 v = ok ? ar[j] : make_float4(0.f, 0.f, 0.f, 0.f);
            __nv_bfloat162 h01 = __floats2bfloat162_rn(v.x, v.y);
            __nv_bfloat162 h23 = __floats2bfloat162_rn(v.z, v.w);
            __nv_bfloat162 l01 = __floats2bfloat162_rn(v.x - __low2float(h01), v.y - __high2float(h01));
            __nv_bfloat162 l23 = __floats2bfloat162_rn(v.z - __low2float(h23), v.w - __high2float(h23));
            dh[2 * j]     = *reinterpret_cast<uint32_t*>(&h01);
            dh[2 * j + 1] = *reinterpret_cast<uint32_t*>(&h23);
            dl[2 * j]     = *reinterpret_cast<uint32_t*>(&l01);
            dl[2 * j + 1] = *reinterpret_cast<uint32_t*>(&l23);
        }
    }
    __syncthreads();

    int w = tid >> 5, l = tid & 31;
    int g = l >> 2, q = l & 3;

    float acc[16][4];
#pragma unroll
    for (int nt = 0; nt < 16; nt++)
#pragma unroll
        for (int i = 0; i < 4; i++) acc[nt][i] = 0.0f;

    int arow = w * 16 + g;

    for (int kt = 0; kt < 8; kt++) {
        int kw = kt * 8 + q;
        uint32_t a0h = Ahi[arow * PADW + kw];
        uint32_t a1h = Ahi[(arow + 8) * PADW + kw];
        uint32_t a2h = Ahi[arow * PADW + kw + 4];
        uint32_t a3h = Ahi[(arow + 8) * PADW + kw + 4];
        uint32_t a0l = Alo[arow * PADW + kw];
        uint32_t a1l = Alo[(arow + 8) * PADW + kw];
        uint32_t a2l = Alo[arow * PADW + kw + 4];
        uint32_t a3l = Alo[(arow + 8) * PADW + kw + 4];

        uint32_t bh[16][2];
#pragma unroll
        for (int nt = 0; nt < 16; nt++) {
            int n = nt * 8 + g;
            bh[nt][0] = Bhi[n * PADW + kw];
            bh[nt][1] = Bhi[n * PADW + kw + 4];
            mma_bf16(acc[nt], a0h, a1h, a2h, a3h, bh[nt][0], bh[nt][1]);
        }
#pragma unroll
        for (int nt = 0; nt < 16; nt++)
            mma_bf16(acc[nt], a0l, a1l, a2l, a3l, bh[nt][0], bh[nt][1]);
#pragma unroll
        for (int nt = 0; nt < 16; nt++) {
            int n = nt * 8 + g;
            uint32_t b0 = Blo[n * PADW + kw];
            uint32_t b1 = Blo[n * PADW + kw + 4];
            mma_bf16(acc[nt], a0h, a1h, a2h, a3h, b0, b1);
        }
    }

    int r0 = blockIdx.x * 128 + w * 16 + g;
#pragma unroll
    for (int nt = 0; nt < 16; nt++) {
        int c = nt * 8 + q * 2;
        if (r0 < NN)
            *reinterpret_cast<float2*>(&g_h[(size_t)r0 * DD + c]) =
                make_float2(acc[nt][0], acc[nt][1]);
        if (r0 + 8 < NN)
            *reinterpret_cast<float2*>(&g_h[(size_t)(r0 + 8) * DD + c]) =
                make_float2(acc[nt][2], acc[nt][3]);
    }
}

// ================= aggregate: warp per node, no atomics =================
__global__ __launch_bounds__(256)
void agg_kernel(const float* __restrict__ b, float* __restrict__ outbuf,
                int dst_sel, int do_relu) {
    int gw = (blockIdx.x * blockDim.x + threadIdx.x) >> 5;
    int lane = threadIdx.x & 31;
    if (gw >= NN) return;

    float* __restrict__ dstp = dst_sel ? outbuf : g_agg;
    const float4* __restrict__ h4 = reinterpret_cast<const float4*>(g_h);

    int beg = g_off[gw] + g_bsum[gw >> 9];
    int end = (gw + 1 < NN) ? (g_off[gw + 1] + g_bsum[(gw + 1) >> 9]) : EE;

    float di = g_dinv[gw];
    float d2 = di * di;
    float4 self = h4[gw * 32 + lane];
    float4 bb = *reinterpret_cast<const float4*>(&b[lane * 4]);
    float4 acc;
    acc.x = d2 * self.x + bb.x;
    acc.y = d2 * self.y + bb.y;
    acc.z = d2 * self.z + bb.z;
    acc.w = d2 * self.w + bb.w;

    for (int e = beg; e < end; e++) {
        int src = g_esrc[e];
        float nrm = g_enorm[e];
        float4 v = h4[src * 32 + lane];
        acc.x += nrm * v.x;
        acc.y += nrm * v.y;
        acc.z += nrm * v.z;
        acc.w += nrm * v.w;
    }

    if (do_relu) {
        acc.x = fmaxf(acc.x, 0.f);
        acc.y = fmaxf(acc.y, 0.f);
        acc.z = fmaxf(acc.z, 0.f);
        acc.w = fmaxf(acc.w, 0.f);
    }
    *reinterpret_cast<float4*>(&dstp[gw * DD + lane * 4]) = acc;
}

// ================= launch =================
extern "C" void kernel_launch(void* const* d_in, const int* in_sizes, int n_in,
                              void* d_out, int out_size) {
    const float* x  = (const float*)d_in[0];
    const int*   ei = (const int*)d_in[1];     // int32 (jax x64 disabled)
    const float* ew = (const float*)d_in[2];
    const float* W1 = (const float*)d_in[3];
    const float* b1 = (const float*)d_in[4];
    const float* W2 = (const float*)d_in[5];
    const float* b2 = (const float*)d_in[6];
    float* out = (float*)d_out;

    // one-time setup (first call is the uncaptured correctness run; no device
    // memory is allocated by these; launched work is identical every call)
    static cudaStream_t s2;
    static cudaEvent_t ev_fork, ev_join;
    static bool once = false;
    if (!once) {
        cudaFuncSetAttribute(gemm_mma_kernel,
                             cudaFuncAttributeMaxDynamicSharedMemorySize, GEMM_SMEM);
        cudaStreamCreateWithFlags(&s2, cudaStreamNonBlocking);
        cudaEventCreateWithFlags(&ev_fork, cudaEventDisableTiming);
        cudaEventCreateWithFlags(&ev_join, cudaEventDisableTiming);
        once = true;
    }

    const int NB_N  = (NN + 255) / 256;        // covers 2*DD*DD = 32768 too
    const int NB_E  = (EE + 255) / 256;
    const int NB_AG = (NN * 32 + 255) / 256;
    const int NB_GM = (NN + 127) / 128;        // 391 tiles

    // ---- prologue ----
    initconv_kernel<<<NB_N, 256>>>(W1, W2);

    // fork: gemm1 (depends only on initconv + x) runs concurrent with CSR build
    cudaEventRecord(ev_fork, 0);
    cudaStreamWaitEvent(s2, ev_fork, 0);
    gemm_mma_kernel<<<NB_GM, 256, GEMM_SMEM, s2>>>(x, 0);
    cudaEventRecord(ev_join, s2);

    // main stream: CSR build
    deg_hist_kernel<<<NB_E, 256>>>(ei, ew);
    scan1_kernel<<<NSCAN, SCAN_B>>>();         // includes block-sum scan (last block)
    fill_kernel<<<NB_E, 256>>>(ei, ew);

    // join: agg1 needs both fill (stream order) and gemm1 (event)
    cudaStreamWaitEvent(0, ev_join, 0);

    // ---- layer 1 aggregate ----
    agg_kernel<<<NB_AG, 256>>>(b1, out, 0, 1);

    // ---- layer 2 ----
    gemm_mma_kernel<<<NB_GM, 256, GEMM_SMEM>>>(x, 1);
    agg_kernel<<<NB_AG, 256>>>(b2, out, 1, 0);
}

// round 16
// speedup vs baseline: 5.1247x; 1.0574x over previous
#include <cuda_runtime.h>
#include <cuda_bf16.h>
#include <cuda_fp16.h>
#include <cstdint>

#define NN 50000
#define EE 600000
#define DD 128

#define SCAN_B 512
#define NSCAN ((NN + SCAN_B - 1) / SCAN_B)   // 98 blocks

// ---- scratch (device globals) ----
__device__ float g_dinv[NN];
__device__ int   g_cnt[NN];
__device__ int   g_off[NN];      // per-block exclusive scan (block offset added by consumers)
__device__ int   g_bsum[NSCAN];  // block totals, then exclusive scan of them
__device__ int   g_ticket;       // last-block detection for fused scan
__device__ int   g_esrc[EE];
__device__ float g_enorm[EE];
__device__ __half g_h[NN * DD];                   // GEMM output, fp16 (gather payload)
__device__ float g_agg[NN * DD];                  // layer-1 activation (fp32)
__device__ __nv_bfloat16 g_wimg[2][2][DD * DD];   // [layer][hi/lo] W^T as [n][k]

// ========== fused init: zero cnt/dinv/ticket + W split-bf16 conversion ==========
__global__ void initconv_kernel(const float* __restrict__ W1, const float* __restrict__ W2) {
    int i = blockIdx.x * blockDim.x + threadIdx.x;
    if (i == 0) g_ticket = 0;
    if (i < NN) { g_cnt[i] = 0; g_dinv[i] = 0.0f; }
    if (i < 2 * DD * DD) {
        int layer = i >> 14;
        int kn = i & (DD * DD - 1);
        int k = kn >> 7, n = kn & 127;
        const float* W = layer ? W2 : W1;
        float v = W[k * DD + n];
        __nv_bfloat16 hi = __float2bfloat16(v);
        __nv_bfloat16 lo = __float2bfloat16(v - __bfloat162float(hi));
        g_wimg[layer][0][n * DD + k] = hi;
        g_wimg[layer][1][n * DD + k] = lo;
    }
}

__global__ void deg_hist_kernel(const int* __restrict__ ei, const float* __restrict__ ew) {
    int e = blockIdx.x * blockDim.x + threadIdx.x;
    if (e < EE) {
        int dst = ei[EE + e];
        atomicAdd(&g_dinv[dst], ew[e]);
        atomicAdd(&g_cnt[dst], 1);
    }
}

// per-block exclusive scan of g_cnt -> g_off ; block totals -> g_bsum.
// fused: dinv finalize + cnt reset + (last block) exclusive scan of g_bsum.
__global__ void scan1_kernel() {
    __shared__ int s[SCAN_B];
    __shared__ int isLast;
    int tid = threadIdx.x;
    int i = blockIdx.x * SCAN_B + tid;
    int v = (i < NN) ? g_cnt[i] : 0;
    s[tid] = v;
    __syncthreads();
#pragma unroll
    for (int d = 1; d < SCAN_B; d <<= 1) {
        int t = (tid >= d) ? s[tid - d] : 0;
        __syncthreads();
        s[tid] += t;
        __syncthreads();
    }
    if (i < NN) {
        g_off[i] = s[tid] - v;
        g_cnt[i] = 0;
        g_dinv[i] = rsqrtf(g_dinv[i] + 1.0f);
    }
    if (tid == SCAN_B - 1) g_bsum[blockIdx.x] = s[tid];

    // last-block: exclusive scan of the NSCAN block sums (replaces scan2 launch)
    __threadfence();
    if (tid == 0) isLast = (atomicAdd(&g_ticket, 1) == gridDim.x - 1);
    __syncthreads();
    if (isLast) {
        int bv = (tid < NSCAN) ? g_bsum[tid] : 0;
        s[tid] = (tid < 128) ? bv : 0;
        __syncthreads();
#pragma unroll
        for (int d = 1; d < 128; d <<= 1) {
            int t = (tid >= d && tid < 128) ? s[tid - d] : 0;
            __syncthreads();
            if (tid < 128) s[tid] += t;
            __syncthreads();
        }
        if (tid < NSCAN) g_bsum[tid] = s[tid] - bv;
        if (tid == 0) g_ticket = 0;   // reset for next launch
    }
}

// bucket edges by dst (block offset resolved inline); fuse norm computation
__global__ void fill_kernel(const int* __restrict__ ei, const float* __restrict__ ew) {
    int e = blockIdx.x * blockDim.x + threadIdx.x;
    if (e >= EE) return;
    int src = ei[e];
    int dst = ei[EE + e];
    float nrm = g_dinv[src] * ew[e] * g_dinv[dst];
    int slot = g_off[dst] + g_bsum[dst >> 9] + atomicAdd(&g_cnt[dst], 1);
    g_esrc[slot] = src;
    g_enorm[slot] = nrm;
}

// ============ GEMM via mma.sync bf16 (3-pass split): g_h = A @ W ============
#define PADW 68
#define IMG_W (128 * PADW)
#define GEMM_SMEM (4 * IMG_W * 4)          // 139264 bytes

__device__ __forceinline__ void mma_bf16(float* c, uint32_t a0, uint32_t a1,
                                         uint32_t a2, uint32_t a3,
                                         uint32_t b0, uint32_t b1) {
    asm volatile(
        "mma.sync.aligned.m16n8k16.row.col.f32.bf16.bf16.f32 "
        "{%0,%1,%2,%3}, {%4,%5,%6,%7}, {%8,%9}, {%0,%1,%2,%3};"
        : "+f"(c[0]), "+f"(c[1]), "+f"(c[2]), "+f"(c[3])
        : "r"(a0), "r"(a1), "r"(a2), "r"(a3), "r"(b0), "r"(b1));
}

__global__ void __launch_bounds__(256, 1)
gemm_mma_kernel(const float* __restrict__ x, int layer) {
    extern __shared__ uint32_t sm[];
    uint32_t* Ahi = sm;
    uint32_t* Alo = Ahi + IMG_W;
    uint32_t* Bhi = Alo + IMG_W;
    uint32_t* Blo = Bhi + IMG_W;

    const float* __restrict__ A = layer ? g_agg : x;
    int tid = threadIdx.x;

    {
        const uint32_t* wh = reinterpret_cast<const uint32_t*>(g_wimg[layer][0]);
        const uint32_t* wl = reinterpret_cast<const uint32_t*>(g_wimg[layer][1]);
#pragma unroll
        for (int t = 0; t < 32; t++) {
            int idx = tid + t * 256;
            int n = idx >> 6, k2 = idx & 63;
            Bhi[n * PADW + k2] = wh[idx];
            Blo[n * PADW + k2] = wl[idx];
        }
    }
    {
        int row = tid >> 1, hf = tid & 1;
        int grow = blockIdx.x * 128 + row;
        bool ok = grow < NN;
        const float4* ar = reinterpret_cast<const float4*>(A + (size_t)(ok ? grow : 0) * DD) + hf * 16;
        uint32_t* dh = Ahi + row * PADW + hf * 32;
        uint32_t* dl = Alo + row * PADW + hf * 32;
#pragma unroll
        for (int j = 0; j < 16; j++) {
            float4 v = ok ? ar[j] : make_float4(0.f, 0.f, 0.f, 0.f);
            __nv_bfloat162 h01 = __floats2bfloat162_rn(v.x, v.y);
            __nv_bfloat162 h23 = __floats2bfloat162_rn(v.z, v.w);
            __nv_bfloat162 l01 = __floats2bfloat162_rn(v.x - __low2float(h01), v.y - __high2float(h01));
            __nv_bfloat162 l23 = __floats2bfloat162_rn(v.z - __low2float(h23), v.w - __high2float(h23));
            dh[2 * j]     = *reinterpret_cast<uint32_t*>(&h01);
            dh[2 * j + 1] = *reinterpret_cast<uint32_t*>(&h23);
            dl[2 * j]     = *reinterpret_cast<uint32_t*>(&l01);
            dl[2 * j + 1] = *reinterpret_cast<uint32_t*>(&l23);
        }
    }
    __syncthreads();

    int w = tid >> 5, l = tid & 31;
    int g = l >> 2, q = l & 3;

    float acc[16][4];
#pragma unroll
    for (int nt = 0; nt < 16; nt++)
#pragma unroll
        for (int i = 0; i < 4; i++) acc[nt][i] = 0.0f;

    int arow = w * 16 + g;

    for (int kt = 0; kt < 8; kt++) {
        int kw = kt * 8 + q;
        uint32_t a0h = Ahi[arow * PADW + kw];
        uint32_t a1h = Ahi[(arow + 8) * PADW + kw];
        uint32_t a2h = Ahi[arow * PADW + kw + 4];
        uint32_t a3h = Ahi[(arow + 8) * PADW + kw + 4];
        uint32_t a0l = Alo[arow * PADW + kw];
        uint32_t a1l = Alo[(arow + 8) * PADW + kw];
        uint32_t a2l = Alo[arow * PADW + kw + 4];
        uint32_t a3l = Alo[(arow + 8) * PADW + kw + 4];

        uint32_t bh[16][2];
#pragma unroll
        for (int nt = 0; nt < 16; nt++) {
            int n = nt * 8 + g;
            bh[nt][0] = Bhi[n * PADW + kw];
            bh[nt][1] = Bhi[n * PADW + kw + 4];
            mma_bf16(acc[nt], a0h, a1h, a2h, a3h, bh[nt][0], bh[nt][1]);
        }
#pragma unroll
        for (int nt = 0; nt < 16; nt++)
            mma_bf16(acc[nt], a0l, a1l, a2l, a3l, bh[nt][0], bh[nt][1]);
#pragma unroll
        for (int nt = 0; nt < 16; nt++) {
            int n = nt * 8 + g;
            uint32_t b0 = Blo[n * PADW + kw];
            uint32_t b1 = Blo[n * PADW + kw + 4];
            mma_bf16(acc[nt], a0h, a1h, a2h, a3h, b0, b1);
        }
    }

    // store fp16 pairs (gather payload)
    int r0 = blockIdx.x * 128 + w * 16 + g;
#pragma unroll
    for (int nt = 0; nt < 16; nt++) {
        int c = nt * 8 + q * 2;
        if (r0 < NN)
            *reinterpret_cast<__half2*>(&g_h[(size_t)r0 * DD + c]) =
                __floats2half2_rn(acc[nt][0], acc[nt][1]);
        if (r0 + 8 < NN)
            *reinterpret_cast<__half2*>(&g_h[(size_t)(r0 + 8) * DD + c]) =
                __floats2half2_rn(acc[nt][2], acc[nt][3]);
    }
}

// ================= aggregate: warp per node, no atomics, fp16 gather =================
__global__ __launch_bounds__(256)
void agg_kernel(const float* __restrict__ b, float* __restrict__ outbuf,
                int dst_sel, int do_relu) {
    int gw = (blockIdx.x * blockDim.x + threadIdx.x) >> 5;
    int lane = threadIdx.x & 31;
    if (gw >= NN) return;

    float* __restrict__ dstp = dst_sel ? outbuf : g_agg;
    const uint2* __restrict__ h2 = reinterpret_cast<const uint2*>(g_h);  // 4 halves per uint2

    int beg = g_off[gw] + g_bsum[gw >> 9];
    int end = (gw + 1 < NN) ? (g_off[gw + 1] + g_bsum[(gw + 1) >> 9]) : EE;

    float di = g_dinv[gw];
    float d2 = di * di;
    float4 bb = *reinterpret_cast<const float4*>(&b[lane * 4]);

    uint2 su = h2[gw * 32 + lane];
    float2 s01 = __half22float2(*reinterpret_cast<__half2*>(&su.x));
    float2 s23 = __half22float2(*reinterpret_cast<__half2*>(&su.y));
    float4 acc;
    acc.x = d2 * s01.x + bb.x;
    acc.y = d2 * s01.y + bb.y;
    acc.z = d2 * s23.x + bb.z;
    acc.w = d2 * s23.y + bb.w;

    for (int e = beg; e < end; e++) {
        int src = g_esrc[e];
        float nrm = g_enorm[e];
        uint2 u = h2[src * 32 + lane];
        float2 f01 = __half22float2(*reinterpret_cast<__half2*>(&u.x));
        float2 f23 = __half22float2(*reinterpret_cast<__half2*>(&u.y));
        acc.x += nrm * f01.x;
        acc.y += nrm * f01.y;
        acc.z += nrm * f23.x;
        acc.w += nrm * f23.y;
    }

    if (do_relu) {
        acc.x = fmaxf(acc.x, 0.f);
        acc.y = fmaxf(acc.y, 0.f);
        acc.z = fmaxf(acc.z, 0.f);
        acc.w = fmaxf(acc.w, 0.f);
    }
    *reinterpret_cast<float4*>(&dstp[gw * DD + lane * 4]) = acc;
}

// ================= launch =================
extern "C" void kernel_launch(void* const* d_in, const int* in_sizes, int n_in,
                              void* d_out, int out_size) {
    const float* x  = (const float*)d_in[0];
    const int*   ei = (const int*)d_in[1];     // int32 (jax x64 disabled)
    const float* ew = (const float*)d_in[2];
    const float* W1 = (const float*)d_in[3];
    const float* b1 = (const float*)d_in[4];
    const float* W2 = (const float*)d_in[5];
    const float* b2 = (const float*)d_in[6];
    float* out = (float*)d_out;

    // one-time setup (first call is the uncaptured correctness run; no device
    // memory is allocated by these; launched work is identical every call)
    static cudaStream_t s2;
    static cudaEvent_t ev_fork, ev_join;
    static bool once = false;
    if (!once) {
        cudaFuncSetAttribute(gemm_mma_kernel,
                             cudaFuncAttributeMaxDynamicSharedMemorySize, GEMM_SMEM);
        cudaStreamCreateWithFlags(&s2, cudaStreamNonBlocking);
        cudaEventCreateWithFlags(&ev_fork, cudaEventDisableTiming);
        cudaEventCreateWithFlags(&ev_join, cudaEventDisableTiming);
        once = true;
    }

    const int NB_N  = (NN + 255) / 256;        // covers 2*DD*DD = 32768 too
    const int NB_E  = (EE + 255) / 256;
    const int NB_AG = (NN * 32 + 255) / 256;
    const int NB_GM = (NN + 127) / 128;        // 391 tiles

    // ---- prologue ----
    initconv_kernel<<<NB_N, 256>>>(W1, W2);

    // fork: gemm1 (depends only on initconv + x) runs concurrent with CSR build
    cudaEventRecord(ev_fork, 0);
    cudaStreamWaitEvent(s2, ev_fork, 0);
    gemm_mma_kernel<<<NB_GM, 256, GEMM_SMEM, s2>>>(x, 0);
    cudaEventRecord(ev_join, s2);

    // main stream: CSR build
    deg_hist_kernel<<<NB_E, 256>>>(ei, ew);
    scan1_kernel<<<NSCAN, SCAN_B>>>();         // includes block-sum scan (last block)
    fill_kernel<<<NB_E, 256>>>(ei, ew);

    // join: agg1 needs both fill (stream order) and gemm1 (event)
    cudaStreamWaitEvent(0, ev_join, 0);

    // ---- layer 1 aggregate ----
    agg_kernel<<<NB_AG, 256>>>(b1, out, 0, 1);

    // ---- layer 2 ----
    gemm_mma_kernel<<<NB_GM, 256, GEMM_SMEM>>>(x, 1);
    agg_kernel<<<NB_AG, 256>>>(b2, out, 1, 0);
}